// round 10
// baseline (speedup 1.0000x reference)
#include <cuda_runtime.h>
#include <cuda_bf16.h>
#include <cuda_fp16.h>
#include <math_constants.h>

#define FULL 0xffffffffu

static constexpr int B = 8;
static constexpr int N = 4096;
static constexpr int C = 128;
static constexpr int KNN = 16;

typedef unsigned long long ull;

// scratch (device globals: no allocation allowed)
__device__ __half g_zbn[B * N * C];    // zbn[b][n][c] fp16, n-major rows 256B
__device__ float4 g_xyz4[B * N];       // (x,y,z,|p|^2)
__device__ float4 g_pA[B * N / 2];     // candidate pairs: (x0,x1,y0,y1)
__device__ float4 g_pB[B * N / 2];     // candidate pairs: (z0,z1,w0,w1)
__device__ int    g_idx[B * N * KNN];  // 16 NN indices per query

// ---- f32x2 packed helpers (FFMA2 path; per-lane IEEE rn == scalar) ----
__device__ __forceinline__ ull pk2(float lo, float hi) {
    ull r; asm("mov.b64 %0, {%1, %2};" : "=l"(r) : "f"(lo), "f"(hi)); return r;
}
__device__ __forceinline__ void upk2(ull v, float& lo, float& hi) {
    asm("mov.b64 {%0, %1}, %2;" : "=f"(lo), "=f"(hi) : "l"(v));
}
__device__ __forceinline__ ull mul2(ull a, ull b) {
    ull r; asm("mul.rn.f32x2 %0, %1, %2;" : "=l"(r) : "l"(a), "l"(b)); return r;
}
__device__ __forceinline__ ull add2(ull a, ull b) {
    ull r; asm("add.rn.f32x2 %0, %1, %2;" : "=l"(r) : "l"(a), "l"(b)); return r;
}
__device__ __forceinline__ ull fma2(ull a, ull b, ull c) {
    ull r; asm("fma.rn.f32x2 %0, %1, %2, %3;" : "=l"(r) : "l"(a), "l"(b), "l"(c)); return r;
}

// ---------------------------------------------------------------------------
// Kernel 0: pack xyz + squared norms; also emit pair-packed candidate arrays.
// One thread per point-pair. Grid: B*N/2 / 256.
// ---------------------------------------------------------------------------
__global__ void prep_kernel(const float* __restrict__ xyz)
{
    int i = blockIdx.x * 256 + threadIdx.x;   // pair index over B*N/2
    int j = 2 * i;
    float x0 = xyz[3 * j],     y0 = xyz[3 * j + 1], z0 = xyz[3 * j + 2];
    float x1 = xyz[3 * j + 3], y1 = xyz[3 * j + 4], z1 = xyz[3 * j + 5];
    float w0 = x0 * x0 + y0 * y0 + z0 * z0;
    float w1 = x1 * x1 + y1 * y1 + z1 * z1;
    g_xyz4[j]     = make_float4(x0, y0, z0, w0);
    g_xyz4[j + 1] = make_float4(x1, y1, z1, w1);
    g_pA[i] = make_float4(x0, x1, y0, y1);
    g_pB[i] = make_float4(z0, z1, w0, w1);
}

// ---------------------------------------------------------------------------
// Kernel 1: zbn[b][n][c] = relu(scale_c * (sum_k W[c][k] * x[b][k][n]) + bias_c)
// fp32 math, fp16 store.
// ---------------------------------------------------------------------------
__global__ __launch_bounds__(256) void gemm_bn_relu_kernel(
    const float* __restrict__ x,      // [B][C][N]
    const float* __restrict__ W,      // [C_out][C_in]
    const float* __restrict__ gamma,
    const float* __restrict__ beta,
    const float* __restrict__ rmean,
    const float* __restrict__ rvar)
{
    __shared__ float xs[32][64];    // [k][n]
    __shared__ float ws[32][128];   // [k][c], XOR-swizzled in 4-float units

    const int b  = blockIdx.y;
    const int n0 = blockIdx.x * 64;
    const int tid = threadIdx.x;
    const int tc = tid & 31;
    const int tn = tid >> 5;

    float acc[4][8];
#pragma unroll
    for (int j = 0; j < 4; ++j)
#pragma unroll
        for (int i = 0; i < 8; ++i) acc[j][i] = 0.0f;

    const float* xb = x + (size_t)b * C * N;

    for (int k0 = 0; k0 < C; k0 += 32) {
#pragma unroll
        for (int i = tid; i < 32 * 64; i += 256) {
            int kk = i >> 6, nn = i & 63;
            xs[kk][nn] = xb[(size_t)(k0 + kk) * N + n0 + nn];
        }
#pragma unroll
        for (int i = tid; i < 32 * 128; i += 256) {
            int c = i >> 5, kk = i & 31;
            ws[kk][c ^ ((kk & 7) << 2)] = W[c * C + k0 + kk];
        }
        __syncthreads();

#pragma unroll
        for (int kk = 0; kk < 32; ++kk) {
            float4 wv  = *(const float4*)&ws[kk][((tc ^ (kk & 7)) << 2)];
            float4 xv0 = *(const float4*)&xs[kk][tn * 8];
            float4 xv1 = *(const float4*)&xs[kk][tn * 8 + 4];
            float wj[4] = {wv.x, wv.y, wv.z, wv.w};
            float xi[8] = {xv0.x, xv0.y, xv0.z, xv0.w, xv1.x, xv1.y, xv1.z, xv1.w};
#pragma unroll
            for (int j = 0; j < 4; ++j)
#pragma unroll
                for (int i = 0; i < 8; ++i)
                    acc[j][i] = fmaf(wj[j], xi[i], acc[j][i]);
        }
        __syncthreads();
    }

    const int c0 = tc * 4;
    float sc[4], bi[4];
#pragma unroll
    for (int j = 0; j < 4; ++j) {
        sc[j] = gamma[c0 + j] * rsqrtf(rvar[c0 + j] + 1e-5f);
        bi[j] = beta[c0 + j] - rmean[c0 + j] * sc[j];
    }
#pragma unroll
    for (int i = 0; i < 8; ++i) {
        int n = n0 + tn * 8 + i;
        float ox = fmaxf(fmaf(acc[0][i], sc[0], bi[0]), 0.0f);
        float oy = fmaxf(fmaf(acc[1][i], sc[1], bi[1]), 0.0f);
        float oz = fmaxf(fmaf(acc[2][i], sc[2], bi[2]), 0.0f);
        float ow = fmaxf(fmaf(acc[3][i], sc[3], bi[3]), 0.0f);
        __half2 h01 = __floats2half2_rn(ox, oy);
        __half2 h23 = __floats2half2_rn(oz, ow);
        uint2 u;
        u.x = *reinterpret_cast<unsigned*>(&h01);
        u.y = *reinterpret_cast<unsigned*>(&h23);
        *(uint2*)&g_zbn[((size_t)b * N + n) * C + c0] = u;
    }
}

// ---------------------------------------------------------------------------
// Kernel 2: top-16 KNN, thread-per-(query,split), 4 splits of 1024 candidates.
// 256-thread block = 64 queries x 4 splits. Candidates staged in smem as
// f32x2 PAIRS; phase A computes 8 distances with 5 packed FFMA2-class ops per
// pair (bit-identical per lane to the scalar formula); phase B runs the same
// branch-free accepts. Candidate order / flush boundaries / merge identical
// to R9 -> accepted sets and rel_err must be bit-identical.
// Grid: (N/64, B) = 512 blocks.
// ---------------------------------------------------------------------------
__device__ __forceinline__ void insert16(float (&tv)[16], int (&ti)[16],
                                         float e, int jj)
{
#pragma unroll
    for (int t = 15; t >= 0; --t) {
        bool gt  = tv[t] > e;                   // strict: ties keep incumbent
        bool gtp = (t > 0) && (tv[t - 1] > e);
        float nv = gtp ? tv[t - 1] : e;
        int   ni = gtp ? ti[t - 1] : jj;
        if (gt) { tv[t] = nv; ti[t] = ni; }
    }
}

__global__ __launch_bounds__(256) void knn_kernel()
{
    __shared__ ull    buf[16][256];              // accept buffer, 32KB
    __shared__ float4 tileA[512];                // 4 chunks x 128 pairs, 8KB
    __shared__ float4 tileB[512];                // 8KB
    __shared__ float  sthr[64][5];               // per-query split thresholds

    const int tid  = threadIdx.x;
    const int u    = tid & 63;                   // query slot in block
    const int s    = tid >> 6;                   // split 0..3 (warp-homogeneous)
    const int b    = blockIdx.y;
    const int q    = blockIdx.x * 64 + u;

    // init shared thresholds
    for (int i = tid; i < 64 * 5; i += 256) ((float*)sthr)[i] = CUDART_INF_F;

    const float4* __restrict__ pA = g_pA + (size_t)b * (N / 2);
    const float4* __restrict__ pB = g_pB + (size_t)b * (N / 2);
    const float4 Q = __ldg(&g_xyz4[(size_t)b * N + q]);
    const float qs = Q.w;

    const ull Qx2 = pk2(Q.x, Q.x);
    const ull Qy2 = pk2(Q.y, Q.y);
    const ull Qz2 = pk2(Q.z, Q.z);
    const ull qs2 = pk2(qs, qs);
    const ull n22 = pk2(-2.0f, -2.0f);

    float tv[16]; int ti[16];
#pragma unroll
    for (int t = 0; t < 16; ++t) { tv[t] = CUDART_INF_F; ti[t] = 0; }

    const int lo = s << 10;                      // s * 1024
    const float4* __restrict__ chA = tileA + (s << 7);
    const float4* __restrict__ chB = tileB + (s << 7);

    unsigned addr0 = (unsigned)__cvta_generic_to_shared(&buf[0][0]) + tid * 8u;
    unsigned addr  = addr0;
    const unsigned athr = addr0 + 8u * 2048u;    // trigger: cnt >= 8 (stride 2048)
    float fthr = CUDART_INF_F;

#define KNN_FLUSH() do {                                                      \
        int cnt = (int)((addr - addr0) >> 11);                                \
        int mx  = __reduce_max_sync(FULL, cnt);                               \
        for (int t = 0; t < mx; ++t) {                                        \
            ull e = buf[t][tid];                                              \
            float ed = (t < cnt) ? __uint_as_float((unsigned)(e >> 32))       \
                                 : CUDART_INF_F;                              \
            int   ej = (int)(unsigned)e;                                      \
            insert16(tv, ti, ed, ej);                                         \
        }                                                                     \
        addr = addr0;                                                         \
        sthr[u][s] = tv[15];                                                  \
        fthr = fminf(fminf(sthr[u][0], sthr[u][1]),                           \
                     fminf(sthr[u][2], sthr[u][3]));                          \
    } while (0)

#pragma unroll 1
    for (int it = 0; it < 4; ++it) {
        // ---- stage 4x128 pair tile (coalesced; barriers protect reads) ----
        __syncthreads();
#pragma unroll
        for (int k = 0; k < 2; ++k) {
            int flat = tid + (k << 8);           // 0..511
            int ch = flat >> 7, off = flat & 127;
            int gp = (ch << 9) + (it << 7) + off;
            tileA[flat] = __ldg(&pA[gp]);
            tileB[flat] = __ldg(&pB[gp]);
        }
        __syncthreads();

        const int jbase = lo + (it << 8);
        int pt = 0;                              // pair index within chunk

        if (it == 0) {
            // ---- seed: first 16 candidates (8 pairs), co-executed inserts ----
#pragma unroll 1
            for (int pp = 0; pp < 8; ++pp) {
                float4 a = chA[pp], bb = chB[pp];
                ull dot2 = mul2(Qx2, pk2(a.x, a.y));
                dot2 = fma2(Qy2, pk2(a.z, a.w), dot2);
                dot2 = fma2(Qz2, pk2(bb.x, bb.y), dot2);
                ull base2 = add2(qs2, pk2(bb.z, bb.w));
                ull dd = fma2(n22, dot2, base2);
                float d0, d1; upk2(dd, d0, d1);
                insert16(tv, ti, d0, jbase + 2 * pp);
                insert16(tv, ti, d1, jbase + 2 * pp + 1);
            }
            sthr[u][s] = tv[15];
            fthr = fminf(fminf(sthr[u][0], sthr[u][1]),
                         fminf(sthr[u][2], sthr[u][3]));
            pt = 8;
        }

        // ---- scan chunk: phase A packed distances (4 pairs = 8 cands),
        //      phase B branch-free accepts, flush check per 8 candidates ----
#pragma unroll 1
        for (; pt < 128; pt += 4) {
            float d[8];
#pragma unroll
            for (int pp = 0; pp < 4; ++pp) {
                float4 a = chA[pt + pp], bb = chB[pt + pp];
                ull dot2 = mul2(Qx2, pk2(a.x, a.y));
                dot2 = fma2(Qy2, pk2(a.z, a.w), dot2);
                dot2 = fma2(Qz2, pk2(bb.x, bb.y), dot2);
                ull base2 = add2(qs2, pk2(bb.z, bb.w));
                ull dd = fma2(n22, dot2, base2);
                upk2(dd, d[2 * pp], d[2 * pp + 1]);
            }
#pragma unroll
            for (int uu = 0; uu < 8; ++uu) {
                int j = jbase + 2 * pt + uu;
                unsigned db = __float_as_uint(d[uu]);
                asm volatile(
                    "{\n\t"
                    ".reg .pred p;\n\t"
                    "setp.lt.f32 p, %1, %2;\n\t"
                    "@p st.shared.v2.b32 [%0], {%3, %4};\n\t"
                    "@p add.u32 %0, %0, 2048;\n\t"
                    "}"
                    : "+r"(addr) : "f"(d[uu]), "f"(fthr), "r"(j), "r"(db) : "memory");
            }
            if (__any_sync(FULL, addr >= athr)) KNN_FLUSH();
        }
    }
    // ---- final flush ----
    if (__any_sync(FULL, addr != addr0)) KNN_FLUSH();
#undef KNN_FLUSH

    // ---- merge splits 1..3 into split 0 (ascending split order preserves
    //      lower-index-on-tie). Staging overlays the dead accept buffer. ----
    __syncthreads();                             // all flush reads of buf done
    float (*mD)[3][17] = (float(*)[3][17])&buf[0][0];
    int   (*mI)[3][17] = (int(*)[3][17])((float*)&buf[0][0] + 64 * 3 * 17);

    if (s != 0) {
#pragma unroll
        for (int t = 0; t < 16; ++t) {
            mD[u][s - 1][t] = tv[t];
            mI[u][s - 1][t] = ti[t];
        }
    }
    __syncthreads();
    if (s == 0) {
#pragma unroll 1
        for (int k = 0; k < 3; ++k)
#pragma unroll 1
            for (int t = 0; t < 16; ++t)
                insert16(tv, ti, mD[u][k][t], mI[u][k][t]);

        int* op = g_idx + ((size_t)b * N + q) * KNN;
#pragma unroll
        for (int t = 0; t < 16; ++t) op[t] = ti[t];
    }
}

// ---------------------------------------------------------------------------
// Kernel 3: gather-max over 16 neighbors (fp16 rows, one LDG.64 + 2 HMNMX2
// per row per lane) + transpose to [B][C][N] float.
// Warp per query (4 queries/warp), 256 threads. Grid: (N/32, B).
// ---------------------------------------------------------------------------
__global__ __launch_bounds__(256) void gather_kernel(float* __restrict__ out)
{
    __shared__ float sout[128][33];

    const int b    = blockIdx.y;
    const int n0   = blockIdx.x * 32;
    const int tid  = threadIdx.x;
    const int w    = tid >> 5;
    const int lane = tid & 31;

    const __half* __restrict__ zb = g_zbn + (size_t)b * N * C;

    for (int s = 0; s < 4; ++s) {
        const int ql = w * 4 + s;
        const int n  = n0 + ql;
        int myidx = (lane < 16) ? g_idx[((size_t)b * N + n) * KNN + lane] : 0;

        __half2 m01 = __float2half2_rn(0.0f);   // post-ReLU >= 0
        __half2 m23 = __float2half2_rn(0.0f);
#pragma unroll
        for (int t = 0; t < KNN; t += 2) {
            int j1 = __shfl_sync(FULL, myidx, t);
            int j2 = __shfl_sync(FULL, myidx, t + 1);
            const uint2* r1 = (const uint2*)(zb + ((size_t)j1 << 7));
            const uint2* r2 = (const uint2*)(zb + ((size_t)j2 << 7));
            uint2 u1 = __ldg(&r1[lane]);
            uint2 u2 = __ldg(&r2[lane]);
            m01 = __hmax2(m01, *reinterpret_cast<__half2*>(&u1.x));
            m23 = __hmax2(m23, *reinterpret_cast<__half2*>(&u1.y));
            m01 = __hmax2(m01, *reinterpret_cast<__half2*>(&u2.x));
            m23 = __hmax2(m23, *reinterpret_cast<__half2*>(&u2.y));
        }

        float2 f01 = __half22float2(m01);
        float2 f23 = __half22float2(m23);
        sout[4 * lane + 0][ql] = f01.x;
        sout[4 * lane + 1][ql] = f01.y;
        sout[4 * lane + 2][ql] = f23.x;
        sout[4 * lane + 3][ql] = f23.y;
    }
    __syncthreads();

    float* ob = out + (size_t)b * C * N + n0;
    for (int i = tid; i < 128 * 32; i += 256) {
        int c = i >> 5, nn = i & 31;
        ob[(size_t)c * N + nn] = sout[c][nn];
    }
}

// ---------------------------------------------------------------------------
extern "C" void kernel_launch(void* const* d_in, const int* in_sizes, int n_in,
                              void* d_out, int out_size)
{
    const float* xyz   = (const float*)d_in[0];
    const float* x     = (const float*)d_in[1];
    const float* W     = (const float*)d_in[2];
    const float* gamma = (const float*)d_in[3];
    const float* beta  = (const float*)d_in[4];
    const float* rmean = (const float*)d_in[5];
    const float* rvar  = (const float*)d_in[6];
    float* out = (float*)d_out;

    prep_kernel<<<B * N / 2 / 256, 256>>>(xyz);
    gemm_bn_relu_kernel<<<dim3(N / 64, B), 256>>>(x, W, gamma, beta, rmean, rvar);
    knn_kernel<<<dim3(N / 64, B), 256>>>();
    gather_kernel<<<dim3(N / 32, B), 256>>>(out);
}